// round 2
// baseline (speedup 1.0000x reference)
#include <cuda_runtime.h>
#include <math.h>

#define HBUF 25165824   // 12*32*65536 floats

__device__ float g_hA[HBUF];
__device__ float g_hB[HBUF];
__device__ float g_hC[HBUF];
__device__ float g_spec[HBUF];
__device__ float g_Y[3145728];    // [row=bvc*256+x][32]  (16 re | 16 im)
__device__ float g_Z[3145728];    // [row=bvo*256+x][32]  (16 re | 16 im)
__device__ float g_X1[393216];    // [v][kx32][ky16][b4][c32][ri]
__device__ float g_X2[393216];    // [bvo][kx32][ky16][ri]
__device__ float g_Ef[8192];      // [y][32]: k<16 cos, k>=16 -sin
__device__ float g_E2c[8192];     // [kxidx][x] cos
__device__ float g_E2s[8192];     // [kxidx][x] sin
__device__ float g_EIr[8192];     // [kxidx][x] cos/256
__device__ float g_EIi[8192];     // [kxidx][x] sin/256
__device__ float g_Dy[8192];      // [j32][y] inverse-y real basis
__device__ float g_W1T[8192];     // fc1t_w transposed [j256][c32]

__device__ __forceinline__ float gelu_f(float x) {
    return 0.5f * x * (1.0f + erff(x * 0.70710678118654752440f));
}
__device__ __forceinline__ float* bufsel(int s) {
    if (s == 0) return g_hA;
    if (s == 1) return g_hB;
    if (s == 2) return g_hC;
    return g_spec;
}

// ----------------- basis tables -----------------
__global__ void setup_basis() {
    int x = threadIdx.x;  // 0..255
    for (int k = 0; k < 16; k++) {
        double sv, cv;
        sincospi(((double)(k * x)) / 128.0, &sv, &cv);
        g_Ef[x * 32 + k]      = (float)cv;
        g_Ef[x * 32 + 16 + k] = (float)(-sv);
        double cj = (k == 0) ? 1.0 : 2.0;
        g_Dy[k * 256 + x]        = (float)( cj * cv / 256.0);
        g_Dy[(16 + k) * 256 + x] = (float)(-cj * sv / 256.0);
    }
    for (int j = 0; j < 32; j++) {
        int f = (j < 16) ? j : (224 + j);  // kx = 0..15, 240..255
        double sv, cv;
        sincospi(((double)(f * x)) / 128.0, &sv, &cv);
        g_E2c[j * 256 + x] = (float)cv;
        g_E2s[j * 256 + x] = (float)sv;
        g_EIr[j * 256 + x] = (float)(cv / 256.0);
        g_EIi[j * 256 + x] = (float)(sv / 256.0);
    }
}

__global__ void transposeW1(const float* __restrict__ w) {
    int t = blockIdx.x * 256 + threadIdx.x;  // 8192
    int c = t >> 8, j = t & 255;
    g_W1T[j * 32 + c] = w[t];
}

// ----------------- fc0 lift -----------------
__global__ void __launch_bounds__(256) fc0_kernel(const float* __restrict__ xin,
                                                  const float* __restrict__ w,
                                                  const float* __restrict__ b) {
    __shared__ float sW[384];
    __shared__ float sB[32];
    int tid = threadIdx.x;
    for (int i = tid; i < 384; i += 256) sW[i] = w[i];
    if (tid < 32) sB[tid] = b[tid];
    __syncthreads();
    int q = blockIdx.x * 256 + tid;       // 0..786431
    int bv = q >> 16, p = q & 65535;
    float xv[12];
    const float* xp = xin + (size_t)q * 10;
#pragma unroll
    for (int t = 0; t < 10; t++) xv[t] = xp[t];
    xv[10] = (float)(p >> 8) * (1.0f / 255.0f);
    xv[11] = (float)(p & 255) * (1.0f / 255.0f);
    float* out = g_hA + (size_t)bv * 2097152 + p;
#pragma unroll
    for (int c = 0; c < 32; c++) {
        float acc = sB[c];
#pragma unroll
        for (int t = 0; t < 12; t++) acc += xv[t] * sW[t * 32 + c];
        out[(size_t)c * 65536] = acc;
    }
}

// ----------------- F1: forward y-DFT. rows=(bvc,x), Y[row][32] -----------------
__global__ void __launch_bounds__(256) gemmF1(int s_in) {
    const float* __restrict__ A = bufsel(s_in);
    __shared__ float sA[32][257];
    int tid = threadIdx.x;
    size_t rb = (size_t)blockIdx.x * 32;
    for (int e = tid; e < 8192; e += 256) sA[e >> 8][e & 255] = A[rb * 256 + e];
    __syncthreads();
    int r = tid >> 3, k0 = (tid & 7) * 4;
    float4 acc = make_float4(0.f, 0.f, 0.f, 0.f);
    const float4* Ef4 = (const float4*)g_Ef;
#pragma unroll 4
    for (int y = 0; y < 256; y++) {
        float av = sA[r][y];
        float4 ef = __ldg(&Ef4[y * 8 + (k0 >> 2)]);
        acc.x += av * ef.x; acc.y += av * ef.y;
        acc.z += av * ef.z; acc.w += av * ef.w;
    }
    ((float4*)g_Y)[((rb + r) * 32 + k0) >> 2] = acc;
}

// ----------------- F2: forward x-DFT, per bvc -----------------
__global__ void __launch_bounds__(256) dftxF() {
    __shared__ float sY[8192];
    int tid = threadIdx.x;
    int bvc = blockIdx.x;
    for (int e = tid; e < 8192; e += 256) sY[e] = g_Y[(size_t)bvc * 8192 + e];
    __syncthreads();
    int bv = bvc >> 5, c = bvc & 31;
    int b = bv / 3, v = bv - 3 * b;
    int kx = tid >> 3, ky0 = (tid & 7) * 2;
    float r0 = 0.f, i0 = 0.f, r1 = 0.f, i1 = 0.f;
    const float* Ec = g_E2c + kx * 256;
    const float* Es = g_E2s + kx * 256;
#pragma unroll 4
    for (int x = 0; x < 256; x++) {
        float cc = __ldg(Ec + x), ss = __ldg(Es + x);
        float2 yr = *(float2*)&sY[x * 32 + ky0];
        float2 yi = *(float2*)&sY[x * 32 + 16 + ky0];
        r0 += cc * yr.x + ss * yi.x;  i0 += cc * yi.x - ss * yr.x;
        r1 += cc * yr.y + ss * yi.y;  i1 += cc * yi.y - ss * yr.y;
    }
    float2* x1p = (float2*)g_X1;
    int base2 = (v * 32 + kx) * 16;
    x1p[((base2 + ky0) * 4 + b) * 32 + c] = make_float2(r0, i0);
    x1p[((base2 + ky0 + 1) * 4 + b) * 32 + c] = make_float2(r1, i1);
}

// ----------------- MIX: per-(v,kx) complex 4x32x32 mode mixing -----------------
__global__ void __launch_bounds__(256) mixmodes(const float* __restrict__ w1r,
                                                const float* __restrict__ w1i,
                                                const float* __restrict__ w2r,
                                                const float* __restrict__ w2i) {
    __shared__ float2 sXc[2048];
    __shared__ float sWr[2048], sWi[2048];
    int tid = threadIdx.x;
    int v = blockIdx.x >> 5, kx = blockIdx.x & 31;
    int mx = (kx < 16) ? kx : (kx - 16);
    const float* wr = (kx < 16) ? w1r : w2r;
    const float* wi = (kx < 16) ? w1i : w2i;
    const float2* x1f2 = (const float2*)g_X1;
    for (int e = tid; e < 2048; e += 256) {
        int ky = e >> 7, b = (e >> 5) & 3, i = e & 31;
        sXc[i * 64 + ky * 4 + b] = x1f2[(size_t)(v * 32 + kx) * 2048 + e];
    }
    int o_ = tid >> 6, ky = (tid >> 2) & 15, b = tid & 3;
    for (int oc = 0; oc < 8; oc++) {
        __syncthreads();
        for (int e = tid; e < 2048; e += 256) {
            int i = e >> 6, oo = (e >> 4) & 3, my = e & 15;
            size_t src = (size_t)i * 24576 + (size_t)(oc * 4 + oo) * 768 + v * 256 + mx * 16 + my;
            sWr[e] = wr[src];
            sWi[e] = wi[src];
        }
        __syncthreads();
        float zr = 0.f, zi = 0.f;
#pragma unroll
        for (int i = 0; i < 32; i++) {
            float wrv = sWr[i * 64 + o_ * 16 + ky];
            float wiv = sWi[i * 64 + o_ * 16 + ky];
            float2 xv = sXc[i * 64 + ky * 4 + b];
            zr += xv.x * wrv - xv.y * wiv;
            zi += xv.x * wiv + xv.y * wrv;
        }
        int og = oc * 4 + o_;
        int bvo = (b * 3 + v) * 32 + og;
        ((float2*)g_X2)[(bvo * 32 + kx) * 16 + ky] = make_float2(zr, zi);
    }
}

// ----------------- I1: inverse x-DFT, per bvo -----------------
__global__ void __launch_bounds__(256) dftxI() {
    __shared__ float sF[1024];
    int tid = threadIdx.x;
    int bvo = blockIdx.x;
    for (int e = tid; e < 1024; e += 256) sF[e] = g_X2[(size_t)bvo * 1024 + e];
    __syncthreads();
    int x = tid;
    float gr[16], gi[16];
#pragma unroll
    for (int k = 0; k < 16; k++) { gr[k] = 0.f; gi[k] = 0.f; }
    const float2* sFc = (const float2*)sF;
    for (int kx = 0; kx < 32; kx++) {
        float cc = __ldg(&g_EIr[kx * 256 + x]);
        float ss = __ldg(&g_EIi[kx * 256 + x]);
#pragma unroll
        for (int ky = 0; ky < 16; ky++) {
            float2 f = sFc[kx * 16 + ky];
            gr[ky] += cc * f.x - ss * f.y;
            gi[ky] += cc * f.y + ss * f.x;
        }
    }
    size_t row = (size_t)bvo * 256 + x;
    float4* zp = (float4*)&g_Z[row * 32];
#pragma unroll
    for (int kq = 0; kq < 4; kq++) {
        zp[kq] = make_float4(gr[kq*4], gr[kq*4+1], gr[kq*4+2], gr[kq*4+3]);
        zp[kq+4] = make_float4(gi[kq*4], gi[kq*4+1], gi[kq*4+2], gi[kq*4+3]);
    }
}

// ----------------- I2: inverse y-DFT -> g_spec -----------------
__global__ void __launch_bounds__(256) idfty() {
    __shared__ float sZ[32][32];
    __shared__ float sD[8192];
    int tid = threadIdx.x;
    size_t rb = (size_t)blockIdx.x * 32;
    for (int e = tid; e < 1024; e += 256) sZ[e >> 5][e & 31] = g_Z[rb * 32 + e];
    for (int e = tid; e < 8192; e += 256) sD[e] = g_Dy[e];
    __syncthreads();
    int r = tid >> 3, yg = tid & 7;
    float z[32];
#pragma unroll
    for (int j = 0; j < 32; j++) z[j] = sZ[r][j];
    const float4* sD4 = (const float4*)sD;
    float* out = g_spec + (rb + r) * 256;
#pragma unroll
    for (int k = 0; k < 8; k++) {
        int yq = yg + 8 * k;
        float4 acc = make_float4(0.f, 0.f, 0.f, 0.f);
#pragma unroll
        for (int j = 0; j < 32; j++) {
            float4 d = sD4[j * 64 + yq];
            float zv = z[j];
            acc.x += zv * d.x; acc.y += zv * d.y;
            acc.z += zv * d.z; acc.w += zv * d.w;
        }
        ((float4*)out)[yq] = acc;
    }
}

// ----------------- fused pointwise chain per layer -----------------
__global__ void __launch_bounds__(256) convfuse(int s_t, int s_res, int s_out,
        const float* __restrict__ m1w, const float* __restrict__ m1b,
        const float* __restrict__ m2w, const float* __restrict__ m2b,
        const float* __restrict__ ww,  const float* __restrict__ wb,
        const float* __restrict__ bw,  const float* __restrict__ bb) {
    __shared__ float sM1[1024], sM2T[1024], sWW[1024];
    __shared__ float sB1[32], sB0[32], sBX[32], sBY[32];
    int tid = threadIdx.x;
    for (int e = tid; e < 1024; e += 256) {
        sM1[e] = m1w[e];
        sWW[e] = ww[e];
        sM2T[(e & 31) * 32 + (e >> 5)] = m2w[e];
    }
    if (tid < 32) {
        sB1[tid] = m1b[tid];
        sB0[tid] = m2b[tid] + wb[tid] + bb[tid];
        sBX[tid] = bw[tid * 2];
        sBY[tid] = bw[tid * 2 + 1];
    }
    __syncthreads();
    int q = blockIdx.x * 256 + tid;
    int bv = q >> 16, p = q & 65535;
    float gx = (float)(p >> 8) * (1.0f / 255.0f);
    float gy = (float)(p & 255) * (1.0f / 255.0f);
    size_t base = (size_t)bv * 2097152 + p;
    const float* tp = bufsel(s_t) + base;
    float a[32], acc[32];
#pragma unroll
    for (int c = 0; c < 32; c++) a[c] = tp[(size_t)c * 65536];
#pragma unroll
    for (int o = 0; o < 32; o++) {
        float s = sB0[o] + sBX[o] * gx + sBY[o] * gy;
        const float4* w4 = (const float4*)&sWW[o * 32];
#pragma unroll
        for (int cq = 0; cq < 8; cq++) {
            float4 w = w4[cq];
            s += w.x * a[cq*4] + w.y * a[cq*4+1] + w.z * a[cq*4+2] + w.w * a[cq*4+3];
        }
        acc[o] = s;
    }
#pragma unroll
    for (int c = 0; c < 32; c++) a[c] = g_spec[base + (size_t)c * 65536];
#pragma unroll
    for (int o = 0; o < 32; o++) {
        float s = sB1[o];
        const float4* w4 = (const float4*)&sM1[o * 32];
#pragma unroll
        for (int cq = 0; cq < 8; cq++) {
            float4 w = w4[cq];
            s += w.x * a[cq*4] + w.y * a[cq*4+1] + w.z * a[cq*4+2] + w.w * a[cq*4+3];
        }
        float g = gelu_f(s);
        const float4* m4 = (const float4*)&sM2T[o * 32];
#pragma unroll
        for (int qq = 0; qq < 8; qq++) {
            float4 w = m4[qq];
            acc[qq*4]   += w.x * g; acc[qq*4+1] += w.y * g;
            acc[qq*4+2] += w.z * g; acc[qq*4+3] += w.w * g;
        }
    }
    float* op = bufsel(s_out) + base;
    const float* rp = (s_res >= 0) ? (bufsel(s_res) + base) : (const float*)0;
#pragma unroll
    for (int o = 0; o < 32; o++) {
        float val = gelu_f(acc[o]);
        if (rp) val += rp[(size_t)o * 65536];
        op[(size_t)o * 65536] = val;
    }
}

// ----------------- fc1v: mix over v (3->3), gelu -----------------
__global__ void __launch_bounds__(256) fc1v_kernel(const float* __restrict__ w,
                                                   const float* __restrict__ bvec) {
    int q = blockIdx.x * 256 + threadIdx.x;   // 4*32*65536
    int b = q >> 21, c = (q >> 16) & 31, p = q & 65535;
    float v0 = g_hA[((size_t)((b*3+0)*32 + c)) * 65536 + p];
    float v1 = g_hA[((size_t)((b*3+1)*32 + c)) * 65536 + p];
    float v2 = g_hA[((size_t)((b*3+2)*32 + c)) * 65536 + p];
#pragma unroll
    for (int vo = 0; vo < 3; vo++) {
        float o = v0 * __ldg(&w[vo]) + v1 * __ldg(&w[3+vo]) + v2 * __ldg(&w[6+vo]) + __ldg(&bvec[vo]);
        g_hB[((size_t)((b*3+vo)*32 + c)) * 65536 + p] = gelu_f(o);
    }
}

// ----------------- head: fused fc1t(32->256)+gelu+fc2t(256->10) -----------------
__global__ void __launch_bounds__(256) head_kernel(const float* __restrict__ b1,
                                                   const float* __restrict__ w2,
                                                   const float* __restrict__ b2,
                                                   float* __restrict__ dout) {
    __shared__ float sW1T[8192];
    __shared__ float sW2[2560];
    __shared__ float sB1h[256];
    __shared__ float sB2h[16];
    int tid = threadIdx.x;
    for (int e = tid; e < 8192; e += 256) sW1T[e] = g_W1T[e];
    for (int e = tid; e < 2560; e += 256) sW2[e] = w2[e];
    if (tid < 256) sB1h[tid] = b1[tid];
    if (tid < 10) sB2h[tid] = b2[tid];
    __syncthreads();
    int q = blockIdx.x * 256 + tid;
    int bvo = q >> 16, p = q & 65535;
    size_t base = (size_t)bvo * 2097152 + p;
    float a[32];
#pragma unroll
    for (int c = 0; c < 32; c++) a[c] = g_hB[base + (size_t)c * 65536];
    float o10[10];
#pragma unroll
    for (int s = 0; s < 10; s++) o10[s] = sB2h[s];
    for (int j = 0; j < 256; j++) {
        float u = sB1h[j];
        const float4* w4 = (const float4*)&sW1T[j * 32];
#pragma unroll
        for (int cq = 0; cq < 8; cq++) {
            float4 w = w4[cq];
            u += w.x * a[cq*4] + w.y * a[cq*4+1] + w.z * a[cq*4+2] + w.w * a[cq*4+3];
        }
        float g = gelu_f(u);
#pragma unroll
        for (int s = 0; s < 10; s++) o10[s] += g * sW2[j * 10 + s];
    }
    float* op = dout + (size_t)bvo * 655360 + (size_t)p * 10;
#pragma unroll
    for (int s = 0; s < 10; s++) op[s] = o10[s];
}

// ----------------- launch -----------------
extern "C" void kernel_launch(void* const* d_in, const int* in_sizes, int n_in,
                              void* d_out, int out_size) {
    const float* x      = (const float*)d_in[0];
    const float* fc0_w  = (const float*)d_in[1];
    const float* fc0_b  = (const float*)d_in[2];
    const float* w1r    = (const float*)d_in[3];
    const float* w1i    = (const float*)d_in[4];
    const float* w2r    = (const float*)d_in[5];
    const float* w2i    = (const float*)d_in[6];
    const float* m1w    = (const float*)d_in[7];
    const float* m1b    = (const float*)d_in[8];
    const float* m2w    = (const float*)d_in[9];
    const float* m2b    = (const float*)d_in[10];
    const float* ww     = (const float*)d_in[11];
    const float* wb     = (const float*)d_in[12];
    const float* bw     = (const float*)d_in[13];
    const float* bb     = (const float*)d_in[14];
    const float* fc1v_w = (const float*)d_in[15];
    const float* fc1v_b = (const float*)d_in[16];
    const float* fc1t_w = (const float*)d_in[17];
    const float* fc1t_b = (const float*)d_in[18];
    const float* fc2t_w = (const float*)d_in[19];
    const float* fc2t_b = (const float*)d_in[20];
    float* out = (float*)d_out;

    setup_basis<<<1, 256>>>();
    transposeW1<<<32, 256>>>(fc1t_w);
    fc0_kernel<<<3072, 256>>>(x, fc0_w, fc0_b);

    const int tin[6]  = {0, 1, 2, 0, 1, 2};
    const int tout[6] = {1, 2, 0, 1, 2, 0};
    const int tres[6] = {-1, -1, 1, -1, -1, 1};
    for (int l = 0; l < 6; l++) {
        gemmF1<<<3072, 256>>>(tin[l]);
        dftxF<<<384, 256>>>();
        mixmodes<<<96, 256>>>(w1r + (size_t)l * 786432, w1i + (size_t)l * 786432,
                              w2r + (size_t)l * 786432, w2i + (size_t)l * 786432);
        dftxI<<<384, 256>>>();
        idfty<<<3072, 256>>>();
        convfuse<<<3072, 256>>>(tin[l], tres[l], tout[l],
                                m1w + l * 1024, m1b + l * 32,
                                m2w + l * 1024, m2b + l * 32,
                                ww + l * 1024,  wb + l * 32,
                                bw + l * 64,    bb + l * 32);
    }
    fc1v_kernel<<<32768, 256>>>(fc1v_w, fc1v_b);
    head_kernel<<<3072, 256>>>(fc1t_b, fc2t_w, fc2t_b, out);
}

// round 3
// speedup vs baseline: 1.4556x; 1.4556x over previous
#include <cuda_runtime.h>
#include <math.h>

#define HBUF 25165824   // 12*32*65536 floats

__device__ float g_hA[HBUF];
__device__ float g_hB[HBUF];
__device__ float g_hC[HBUF];
__device__ float g_spec[HBUF];
__device__ float g_Y[3145728];    // [row=bvc*256+x][32]  (16 re | 16 im)
__device__ float g_Z[3145728];    // [row=bvo*256+x][32]  (16 gr | 16 gi)
__device__ float g_X1[393216];    // [v][kx32][ky16][b4][c32][ri]
__device__ float g_X2[393216];    // [bvo][kx32][ky16][ri]
__device__ float g_Ef[8192];      // [y][32]: k<16 cos, k>=16 -sin
__device__ float g_Dy[8192];      // [j32][y] inverse-y real basis
__device__ float g_E2T[16384];    // [x][64]: m<32 cos(f_m x), m>=32 sin
__device__ float g_EI2[16384];    // [kk64][x]: even cos/256, odd sin/256
__device__ float g_W1T[8192];     // fc1t_w transposed [j256][c32]

typedef unsigned long long u64;

__device__ __forceinline__ u64 pk2(float lo, float hi) {
    u64 r; asm("mov.b64 %0,{%1,%2};" : "=l"(r) : "f"(lo), "f"(hi)); return r;
}
__device__ __forceinline__ void upk2(u64 v, float& lo, float& hi) {
    asm("mov.b64 {%0,%1},%2;" : "=f"(lo), "=f"(hi) : "l"(v));
}
__device__ __forceinline__ u64 fma2(u64 a, u64 b, u64 c) {
    u64 d; asm("fma.rn.f32x2 %0,%1,%2,%3;" : "=l"(d) : "l"(a), "l"(b), "l"(c)); return d;
}

__device__ __forceinline__ float gelu_f(float x) {
    return 0.5f * x * (1.0f + erff(x * 0.70710678118654752440f));
}
__device__ __forceinline__ float* bufsel(int s) {
    if (s == 0) return g_hA;
    if (s == 1) return g_hB;
    if (s == 2) return g_hC;
    return g_spec;
}

// ----------------- basis tables (48 blocks) -----------------
__global__ void setup_basis() {
    int x = threadIdx.x;          // 0..255
    int t = blockIdx.x;           // 0..47
    if (t < 16) {
        int k = t;
        double sv, cv;
        sincospi(((double)(k * x)) / 128.0, &sv, &cv);
        g_Ef[x * 32 + k]      = (float)cv;
        g_Ef[x * 32 + 16 + k] = (float)(-sv);
        double cj = (k == 0) ? 1.0 : 2.0;
        g_Dy[k * 256 + x]        = (float)( cj * cv / 256.0);
        g_Dy[(16 + k) * 256 + x] = (float)(-cj * sv / 256.0);
    } else {
        int j = t - 16;           // 0..31
        int f = (j < 16) ? j : (224 + j);   // kx = 0..15, 240..255
        double sv, cv;
        sincospi(((double)(f * x)) / 128.0, &sv, &cv);
        g_E2T[x * 64 + j]      = (float)cv;
        g_E2T[x * 64 + 32 + j] = (float)sv;
        g_EI2[(2 * j) * 256 + x]     = (float)(cv / 256.0);
        g_EI2[(2 * j + 1) * 256 + x] = (float)(sv / 256.0);
    }
}

__global__ void transposeW1(const float* __restrict__ w) {
    int t = blockIdx.x * 256 + threadIdx.x;  // 8192
    int c = t >> 8, j = t & 255;
    g_W1T[j * 32 + c] = w[t];
}

// ----------------- fc0 lift -----------------
__global__ void __launch_bounds__(256) fc0_kernel(const float* __restrict__ xin,
                                                  const float* __restrict__ w,
                                                  const float* __restrict__ b) {
    __shared__ float sW[384];
    __shared__ float sB[32];
    int tid = threadIdx.x;
    for (int i = tid; i < 384; i += 256) sW[i] = w[i];
    if (tid < 32) sB[tid] = b[tid];
    __syncthreads();
    int q = blockIdx.x * 256 + tid;
    int bv = q >> 16, p = q & 65535;
    float xv[12];
    const float* xp = xin + (size_t)q * 10;
#pragma unroll
    for (int t = 0; t < 10; t++) xv[t] = xp[t];
    xv[10] = (float)(p >> 8) * (1.0f / 255.0f);
    xv[11] = (float)(p & 255) * (1.0f / 255.0f);
    float* out = g_hA + (size_t)bv * 2097152 + p;
#pragma unroll
    for (int c = 0; c < 32; c++) {
        float acc = sB[c];
#pragma unroll
        for (int t = 0; t < 12; t++) acc += xv[t] * sW[t * 32 + c];
        out[(size_t)c * 65536] = acc;
    }
}

// ----------------- F1: y-DFT as tiled GEMM: C[98304][32] = A[98304][256] x Ef[256][32] -----------------
__global__ void __launch_bounds__(256) gemmF1_t(int s_in) {
    const float* __restrict__ A = bufsel(s_in);
    __shared__ float sAT[32 * 260];   // [yy][row] transposed
    __shared__ float sE[32 * 36];     // [yy][k]
    int tid = threadIdx.x;
    size_t rb = (size_t)blockIdx.x * 256;
    int r0 = (tid >> 3) * 8, c0 = (tid & 7) * 4;
    u64 acc2[4][4];
#pragma unroll
    for (int i = 0; i < 4; i++)
#pragma unroll
        for (int j = 0; j < 4; j++) acc2[i][j] = 0ull;

    for (int kt = 0; kt < 8; kt++) {
        int yt = kt * 32;
        __syncthreads();
        const float4* Ag = (const float4*)(A + (rb + tid) * 256 + yt);
#pragma unroll
        for (int i = 0; i < 8; i++) {
            float4 f = Ag[i];
            sAT[(i * 4 + 0) * 260 + tid] = f.x;
            sAT[(i * 4 + 1) * 260 + tid] = f.y;
            sAT[(i * 4 + 2) * 260 + tid] = f.z;
            sAT[(i * 4 + 3) * 260 + tid] = f.w;
        }
#pragma unroll
        for (int i = 0; i < 4; i++) {
            int e = tid + i * 256;
            int yy = e >> 5, k = e & 31;
            sE[yy * 36 + k] = g_Ef[(yt + yy) * 32 + k];
        }
        __syncthreads();
#pragma unroll
        for (int kk = 0; kk < 32; kk++) {
            longlong2 la = *(const longlong2*)&sAT[kk * 260 + r0];
            longlong2 lb = *(const longlong2*)&sAT[kk * 260 + r0 + 4];
            float4 e4 = *(const float4*)&sE[kk * 36 + c0];
            u64 ap[4] = {(u64)la.x, (u64)la.y, (u64)lb.x, (u64)lb.y};
            u64 eb[4] = {pk2(e4.x, e4.x), pk2(e4.y, e4.y), pk2(e4.z, e4.z), pk2(e4.w, e4.w)};
#pragma unroll
            for (int i = 0; i < 4; i++)
#pragma unroll
                for (int j = 0; j < 4; j++) acc2[i][j] = fma2(ap[i], eb[j], acc2[i][j]);
        }
    }
#pragma unroll
    for (int i = 0; i < 4; i++) {
        float lo0, hi0, lo1, hi1, lo2, hi2, lo3, hi3;
        upk2(acc2[i][0], lo0, hi0); upk2(acc2[i][1], lo1, hi1);
        upk2(acc2[i][2], lo2, hi2); upk2(acc2[i][3], lo3, hi3);
        *(float4*)&g_Y[(rb + r0 + 2 * i) * 32 + c0]     = make_float4(lo0, lo1, lo2, lo3);
        *(float4*)&g_Y[(rb + r0 + 2 * i + 1) * 32 + c0] = make_float4(hi0, hi1, hi2, hi3);
    }
}

// ----------------- F2: x-DFT batched per bvc + complex combine -----------------
__global__ void __launch_bounds__(256) dftxF_t() {
    __shared__ float sY[8192];       // [x][32]
    __shared__ float sO[64 * 33];    // [m][n]
    int tid = threadIdx.x;
    int bvc = blockIdx.x;
    const float4* Yg = (const float4*)g_Y + (size_t)bvc * 2048;
#pragma unroll
    for (int i = 0; i < 8; i++) ((float4*)sY)[tid + i * 256] = Yg[tid + i * 256];
    __syncthreads();
    int m0 = (tid >> 3) * 2, c0 = (tid & 7) * 4;
    u64 acc2[4] = {0ull, 0ull, 0ull, 0ull};
#pragma unroll 8
    for (int kk = 0; kk < 256; kk++) {
        u64 am = *(const u64*)&g_E2T[kk * 64 + m0];
        float4 yv = *(const float4*)&sY[kk * 32 + c0];
        acc2[0] = fma2(am, pk2(yv.x, yv.x), acc2[0]);
        acc2[1] = fma2(am, pk2(yv.y, yv.y), acc2[1]);
        acc2[2] = fma2(am, pk2(yv.z, yv.z), acc2[2]);
        acc2[3] = fma2(am, pk2(yv.w, yv.w), acc2[3]);
    }
#pragma unroll
    for (int j = 0; j < 4; j++) {
        float lo, hi;
        upk2(acc2[j], lo, hi);
        sO[m0 * 33 + c0 + j] = lo;
        sO[(m0 + 1) * 33 + c0 + j] = hi;
    }
    __syncthreads();
    int c = bvc & 31, bv = bvc >> 5;
    int b = bv / 3, v = bv - 3 * b;
    float2* X1c = (float2*)g_X1;
#pragma unroll
    for (int t = tid; t < 512; t += 256) {
        int kx = t >> 4, ky = t & 15;
        float re = sO[kx * 33 + ky] + sO[(32 + kx) * 33 + 16 + ky];
        float im = sO[kx * 33 + 16 + ky] - sO[(32 + kx) * 33 + ky];
        X1c[(size_t)(v * 32 + kx) * 2048 + ky * 128 + b * 32 + c] = make_float2(re, im);
    }
}

// ----------------- MIX: per-(v,kx) complex 4x32x32 mode mixing -----------------
__global__ void __launch_bounds__(256) mixmodes(const float* __restrict__ w1r,
                                                const float* __restrict__ w1i,
                                                const float* __restrict__ w2r,
                                                const float* __restrict__ w2i) {
    __shared__ float2 sXc[2048];
    __shared__ float sWr[2048], sWi[2048];
    int tid = threadIdx.x;
    int v = blockIdx.x >> 5, kx = blockIdx.x & 31;
    int mx = (kx < 16) ? kx : (kx - 16);
    const float* wr = (kx < 16) ? w1r : w2r;
    const float* wi = (kx < 16) ? w1i : w2i;
    const float2* x1f2 = (const float2*)g_X1;
    for (int e = tid; e < 2048; e += 256) {
        int ky = e >> 7, b = (e >> 5) & 3, i = e & 31;
        sXc[i * 64 + ky * 4 + b] = x1f2[(size_t)(v * 32 + kx) * 2048 + e];
    }
    int o_ = tid >> 6, ky = (tid >> 2) & 15, b = tid & 3;
    for (int oc = 0; oc < 8; oc++) {
        __syncthreads();
        for (int e = tid; e < 2048; e += 256) {
            int i = e >> 6, oo = (e >> 4) & 3, my = e & 15;
            size_t src = (size_t)i * 24576 + (size_t)(oc * 4 + oo) * 768 + v * 256 + mx * 16 + my;
            sWr[e] = wr[src];
            sWi[e] = wi[src];
        }
        __syncthreads();
        float zr = 0.f, zi = 0.f;
#pragma unroll
        for (int i = 0; i < 32; i++) {
            float wrv = sWr[i * 64 + o_ * 16 + ky];
            float wiv = sWi[i * 64 + o_ * 16 + ky];
            float2 xv = sXc[i * 64 + ky * 4 + b];
            zr += xv.x * wrv - xv.y * wiv;
            zi += xv.x * wiv + xv.y * wrv;
        }
        int og = oc * 4 + o_;
        int bvo = (b * 3 + v) * 32 + og;
        ((float2*)g_X2)[(bvo * 32 + kx) * 16 + ky] = make_float2(zr, zi);
    }
}

// ----------------- I1: inverse x-DFT batched per bvo -----------------
__global__ void __launch_bounds__(256) dftxI_t() {
    __shared__ float sG[64 * 32];    // [kk][n]: n = 16 for gr source, 16 for gi
    int tid = threadIdx.x;
    int bvo = blockIdx.x;
    const float2* F = (const float2*)g_X2 + (size_t)bvo * 512;
#pragma unroll
    for (int t = tid; t < 512; t += 256) {
        int kx = t >> 4, ky = t & 15;
        float2 f = F[t];
        sG[(2 * kx) * 32 + ky]          = f.x;
        sG[(2 * kx) * 32 + 16 + ky]     = f.y;
        sG[(2 * kx + 1) * 32 + ky]      = -f.y;
        sG[(2 * kx + 1) * 32 + 16 + ky] = f.x;
    }
    __syncthreads();
    int x0 = (tid >> 3) * 8, c0 = (tid & 7) * 4;
    u64 acc2[4][4];
#pragma unroll
    for (int i = 0; i < 4; i++)
#pragma unroll
        for (int j = 0; j < 4; j++) acc2[i][j] = 0ull;
#pragma unroll 16
    for (int kk = 0; kk < 64; kk++) {
        longlong2 la = *(const longlong2*)&g_EI2[kk * 256 + x0];
        longlong2 lb = *(const longlong2*)&g_EI2[kk * 256 + x0 + 4];
        float4 d = *(const float4*)&sG[kk * 32 + c0];
        u64 ap[4] = {(u64)la.x, (u64)la.y, (u64)lb.x, (u64)lb.y};
        u64 db[4] = {pk2(d.x, d.x), pk2(d.y, d.y), pk2(d.z, d.z), pk2(d.w, d.w)};
#pragma unroll
        for (int i = 0; i < 4; i++)
#pragma unroll
            for (int j = 0; j < 4; j++) acc2[i][j] = fma2(ap[i], db[j], acc2[i][j]);
    }
#pragma unroll
    for (int i = 0; i < 4; i++) {
        float lo0, hi0, lo1, hi1, lo2, hi2, lo3, hi3;
        upk2(acc2[i][0], lo0, hi0); upk2(acc2[i][1], lo1, hi1);
        upk2(acc2[i][2], lo2, hi2); upk2(acc2[i][3], lo3, hi3);
        size_t row = (size_t)bvo * 256 + x0 + 2 * i;
        *(float4*)&g_Z[row * 32 + c0]       = make_float4(lo0, lo1, lo2, lo3);
        *(float4*)&g_Z[(row + 1) * 32 + c0] = make_float4(hi0, hi1, hi2, hi3);
    }
}

// ----------------- I2: inverse y-DFT as tiled GEMM: C[98304][256] = Z[98304][32] x Dy[32][256] -----------------
__global__ void __launch_bounds__(256) idfty_t() {
    __shared__ float sZT[32 * 132];  // [k][row]
    __shared__ float sD[32 * 64];    // [k][y]
    int tid = threadIdx.x;
    size_t rb = (size_t)(blockIdx.x >> 2) * 128;
    int cb = (blockIdx.x & 3) * 64;
    const float4* Zg = (const float4*)g_Z;
#pragma unroll
    for (int i = 0; i < 4; i++) {
        int e = tid + i * 256;
        int kq = e >> 7, row = e & 127;
        float4 f = Zg[(rb + row) * 8 + kq];
        sZT[(kq * 4 + 0) * 132 + row] = f.x;
        sZT[(kq * 4 + 1) * 132 + row] = f.y;
        sZT[(kq * 4 + 2) * 132 + row] = f.z;
        sZT[(kq * 4 + 3) * 132 + row] = f.w;
    }
#pragma unroll
    for (int i = 0; i < 8; i++) {
        int e = tid + i * 256;
        int kk = e >> 6, cq = e & 63;
        sD[kk * 64 + cq] = g_Dy[kk * 256 + cb + cq];
    }
    __syncthreads();
    int r0 = (tid >> 4) * 8, c0 = (tid & 15) * 4;
    u64 acc2[4][4];
#pragma unroll
    for (int i = 0; i < 4; i++)
#pragma unroll
        for (int j = 0; j < 4; j++) acc2[i][j] = 0ull;
#pragma unroll
    for (int kk = 0; kk < 32; kk++) {
        longlong2 la = *(const longlong2*)&sZT[kk * 132 + r0];
        longlong2 lb = *(const longlong2*)&sZT[kk * 132 + r0 + 4];
        float4 d = *(const float4*)&sD[kk * 64 + c0];
        u64 ap[4] = {(u64)la.x, (u64)la.y, (u64)lb.x, (u64)lb.y};
        u64 db[4] = {pk2(d.x, d.x), pk2(d.y, d.y), pk2(d.z, d.z), pk2(d.w, d.w)};
#pragma unroll
        for (int i = 0; i < 4; i++)
#pragma unroll
            for (int j = 0; j < 4; j++) acc2[i][j] = fma2(ap[i], db[j], acc2[i][j]);
    }
#pragma unroll
    for (int i = 0; i < 4; i++) {
        float lo0, hi0, lo1, hi1, lo2, hi2, lo3, hi3;
        upk2(acc2[i][0], lo0, hi0); upk2(acc2[i][1], lo1, hi1);
        upk2(acc2[i][2], lo2, hi2); upk2(acc2[i][3], lo3, hi3);
        size_t row = rb + r0 + 2 * i;
        *(float4*)&g_spec[row * 256 + cb + c0]       = make_float4(lo0, lo1, lo2, lo3);
        *(float4*)&g_spec[(row + 1) * 256 + cb + c0] = make_float4(hi0, hi1, hi2, hi3);
    }
}

// ----------------- fused pointwise chain per layer (f32x2) -----------------
__global__ void __launch_bounds__(256) convfuse(int s_t, int s_res, int s_out,
        const float* __restrict__ m1w, const float* __restrict__ m1b,
        const float* __restrict__ m2w, const float* __restrict__ m2b,
        const float* __restrict__ ww,  const float* __restrict__ wb,
        const float* __restrict__ bw,  const float* __restrict__ bb) {
    __shared__ float sM1[1024], sM2T[1024], sWW[1024];
    __shared__ float sB1[32], sB0[32], sBX[32], sBY[32];
    int tid = threadIdx.x;
    for (int e = tid; e < 1024; e += 256) {
        sM1[e] = m1w[e];
        sWW[e] = ww[e];
        sM2T[(e & 31) * 32 + (e >> 5)] = m2w[e];
    }
    if (tid < 32) {
        sB1[tid] = m1b[tid];
        sB0[tid] = m2b[tid] + wb[tid] + bb[tid];
        sBX[tid] = bw[tid * 2];
        sBY[tid] = bw[tid * 2 + 1];
    }
    __syncthreads();
    int q = blockIdx.x * 256 + tid;
    int bv = q >> 16, p = q & 65535;
    float gx = (float)(p >> 8) * (1.0f / 255.0f);
    float gy = (float)(p & 255) * (1.0f / 255.0f);
    size_t base = (size_t)bv * 2097152 + p;
    const float* tp = bufsel(s_t) + base;
    float a[32];
    u64 ap[16];
#pragma unroll
    for (int c = 0; c < 32; c++) a[c] = tp[(size_t)c * 65536];
#pragma unroll
    for (int c = 0; c < 16; c++) ap[c] = pk2(a[2 * c], a[2 * c + 1]);
    float r1[32];
#pragma unroll
    for (int o = 0; o < 32; o++) {
        u64 sa = pk2(sB0[o] + sBX[o] * gx + sBY[o] * gy, 0.f);
        u64 sb = 0ull;
        const u64* wp = (const u64*)&sWW[o * 32];
#pragma unroll
        for (int c = 0; c < 16; c += 2) {
            sa = fma2(wp[c], ap[c], sa);
            sb = fma2(wp[c + 1], ap[c + 1], sb);
        }
        float l0, h0, l1, h1;
        upk2(sa, l0, h0); upk2(sb, l1, h1);
        r1[o] = (l0 + h0) + (l1 + h1);
    }
    u64 acc2[16];
#pragma unroll
    for (int c = 0; c < 16; c++) acc2[c] = pk2(r1[2 * c], r1[2 * c + 1]);
#pragma unroll
    for (int c = 0; c < 32; c++) a[c] = g_spec[base + (size_t)c * 65536];
#pragma unroll
    for (int c = 0; c < 16; c++) ap[c] = pk2(a[2 * c], a[2 * c + 1]);
#pragma unroll
    for (int o = 0; o < 32; o++) {
        u64 sa = pk2(sB1[o], 0.f);
        u64 sb = 0ull;
        const u64* wp = (const u64*)&sM1[o * 32];
#pragma unroll
        for (int c = 0; c < 16; c += 2) {
            sa = fma2(wp[c], ap[c], sa);
            sb = fma2(wp[c + 1], ap[c + 1], sb);
        }
        float l0, h0, l1, h1;
        upk2(sa, l0, h0); upk2(sb, l1, h1);
        float g = gelu_f((l0 + h0) + (l1 + h1));
        u64 gg = pk2(g, g);
        const u64* mp = (const u64*)&sM2T[o * 32];
#pragma unroll
        for (int c = 0; c < 16; c++) acc2[c] = fma2(mp[c], gg, acc2[c]);
    }
    float* op = bufsel(s_out) + base;
    const float* rp = (s_res >= 0) ? (bufsel(s_res) + base) : (const float*)0;
#pragma unroll
    for (int c = 0; c < 16; c++) {
        float lo, hi;
        upk2(acc2[c], lo, hi);
        float v0 = gelu_f(lo), v1 = gelu_f(hi);
        if (rp) {
            v0 += rp[(size_t)(2 * c) * 65536];
            v1 += rp[(size_t)(2 * c + 1) * 65536];
        }
        op[(size_t)(2 * c) * 65536]     = v0;
        op[(size_t)(2 * c + 1) * 65536] = v1;
    }
}

// ----------------- head: fused fc1v + fc1t + gelu + fc2t -----------------
__global__ void __launch_bounds__(256) head_kernel(const float* __restrict__ vw,
                                                   const float* __restrict__ vb,
                                                   const float* __restrict__ b1,
                                                   const float* __restrict__ w2,
                                                   const float* __restrict__ b2,
                                                   float* __restrict__ dout) {
    __shared__ float sW1T[8192];
    __shared__ float sW2[2560];
    __shared__ float sB1h[256];
    int tid = threadIdx.x;
    for (int e = tid; e < 8192; e += 256) sW1T[e] = g_W1T[e];
    for (int e = tid; e < 2560; e += 256) sW2[e] = w2[e];
    sB1h[tid] = b1[tid];
    __syncthreads();
    int q = blockIdx.x * 256 + tid;
    int bvo = q >> 16, p = q & 65535;
    int b = bvo / 3, vo = bvo - 3 * b;
    float w0 = __ldg(&vw[vo]), w1 = __ldg(&vw[3 + vo]), w2v = __ldg(&vw[6 + vo]);
    float vbias = __ldg(&vb[vo]);
    const float* h0 = g_hA + (size_t)(b * 3 + 0) * 2097152 + p;
    const float* h1 = g_hA + (size_t)(b * 3 + 1) * 2097152 + p;
    const float* h2 = g_hA + (size_t)(b * 3 + 2) * 2097152 + p;
    float a[32];
#pragma unroll
    for (int c = 0; c < 32; c++) {
        float t = h0[(size_t)c * 65536] * w0 + h1[(size_t)c * 65536] * w1
                + h2[(size_t)c * 65536] * w2v + vbias;
        a[c] = gelu_f(t);
    }
    u64 ap[16];
#pragma unroll
    for (int c = 0; c < 16; c++) ap[c] = pk2(a[2 * c], a[2 * c + 1]);
    u64 o2[5];
#pragma unroll
    for (int s = 0; s < 5; s++) o2[s] = pk2(__ldg(&b2[2 * s]), __ldg(&b2[2 * s + 1]));
    for (int j = 0; j < 256; j++) {
        u64 ua = pk2(sB1h[j], 0.f);
        u64 ub = 0ull;
        const u64* wp = (const u64*)&sW1T[j * 32];
#pragma unroll
        for (int c = 0; c < 16; c += 2) {
            ua = fma2(wp[c], ap[c], ua);
            ub = fma2(wp[c + 1], ap[c + 1], ub);
        }
        float l0, h0v, l1, h1v;
        upk2(ua, l0, h0v); upk2(ub, l1, h1v);
        float g = gelu_f((l0 + h0v) + (l1 + h1v));
        u64 gg = pk2(g, g);
        const u64* w2p = (const u64*)&sW2[j * 10];
#pragma unroll
        for (int s = 0; s < 5; s++) o2[s] = fma2(w2p[s], gg, o2[s]);
    }
    float2* op = (float2*)(dout + (size_t)bvo * 655360 + (size_t)p * 10);
#pragma unroll
    for (int s = 0; s < 5; s++) {
        float lo, hi;
        upk2(o2[s], lo, hi);
        op[s] = make_float2(lo, hi);
    }
}

// ----------------- launch -----------------
extern "C" void kernel_launch(void* const* d_in, const int* in_sizes, int n_in,
                              void* d_out, int out_size) {
    const float* x      = (const float*)d_in[0];
    const float* fc0_w  = (const float*)d_in[1];
    const float* fc0_b  = (const float*)d_in[2];
    const float* w1r    = (const float*)d_in[3];
    const float* w1i    = (const float*)d_in[4];
    const float* w2r    = (const float*)d_in[5];
    const float* w2i    = (const float*)d_in[6];
    const float* m1w    = (const float*)d_in[7];
    const float* m1b    = (const float*)d_in[8];
    const float* m2w    = (const float*)d_in[9];
    const float* m2b    = (const float*)d_in[10];
    const float* ww     = (const float*)d_in[11];
    const float* wb     = (const float*)d_in[12];
    const float* bw     = (const float*)d_in[13];
    const float* bb     = (const float*)d_in[14];
    const float* fc1v_w = (const float*)d_in[15];
    const float* fc1v_b = (const float*)d_in[16];
    const float* fc1t_w = (const float*)d_in[17];
    const float* fc1t_b = (const float*)d_in[18];
    const float* fc2t_w = (const float*)d_in[19];
    const float* fc2t_b = (const float*)d_in[20];
    float* out = (float*)d_out;

    setup_basis<<<48, 256>>>();
    transposeW1<<<32, 256>>>(fc1t_w);
    fc0_kernel<<<3072, 256>>>(x, fc0_w, fc0_b);

    const int tin[6]  = {0, 1, 2, 0, 1, 2};
    const int tout[6] = {1, 2, 0, 1, 2, 0};
    const int tres[6] = {-1, -1, 1, -1, -1, 1};
    for (int l = 0; l < 6; l++) {
        gemmF1_t<<<384, 256>>>(tin[l]);
        dftxF_t<<<384, 256>>>();
        mixmodes<<<96, 256>>>(w1r + (size_t)l * 786432, w1i + (size_t)l * 786432,
                              w2r + (size_t)l * 786432, w2i + (size_t)l * 786432);
        dftxI_t<<<384, 256>>>();
        idfty_t<<<3072, 256>>>();
        convfuse<<<3072, 256>>>(tin[l], tres[l], tout[l],
                                m1w + l * 1024, m1b + l * 32,
                                m2w + l * 1024, m2b + l * 32,
                                ww + l * 1024,  wb + l * 32,
                                bw + l * 64,    bb + l * 32);
    }
    head_kernel<<<3072, 256>>>(fc1v_w, fc1v_b, fc1t_b, fc2t_w, fc2t_b, out);
}